// round 11
// baseline (speedup 1.0000x reference)
#include <cuda_runtime.h>
#include <cstdint>

#define Bb   8
#define Tt   4096
#define Dd   768
#define Hh   12
#define HDd  64
#define KSp  32
#define D3   2304

#define NSEG 32
#define TSEG 128
#define TCH  16
#define CHUNKS (TSEG / TCH)   // 8

typedef unsigned long long u64;

// ---------------- scratch ----------------
__device__ float g_partial[NSEG * Bb * KSp * Dd];   // 25.2 MB (L2-resident)
__device__ float g_xs[Bb * KSp * Dd];
__device__ float g_qkv[Bb * KSp * D3];
__device__ float g_vg[Bb * KSp * Dd];
__device__ float g_y[Bb * KSp * Dd];

// ---------------- packed f32x2 ----------------
__device__ __forceinline__ u64 pk2(float lo, float hi) {
    u64 r;
    asm("mov.b64 %0, {%1, %2};" : "=l"(r) : "f"(lo), "f"(hi));
    return r;
}
__device__ __forceinline__ void fma2(u64& d, u64 a, u64 b) {
    asm("fma.rn.f32x2 %0, %1, %2, %0;" : "+l"(d) : "l"(a), "l"(b));
}

// ---------------- tf32 helpers (verified via k_expand, R8) ----------------
__device__ __forceinline__ void tf32_split(float x, uint32_t& hi, uint32_t& lo) {
    uint32_t h;
    asm("cvt.rna.tf32.f32 %0, %1;" : "=r"(h) : "f"(x));
    float r = x - __uint_as_float(h);
    asm("cvt.rna.tf32.f32 %0, %1;" : "=r"(lo) : "f"(r));
    hi = h;
}
__device__ __forceinline__ void mma_tf32(float* c, const uint32_t* a,
                                         const uint32_t* b) {
    asm("mma.sync.aligned.m16n8k8.row.col.f32.tf32.tf32.f32 "
        "{%0,%1,%2,%3}, {%4,%5,%6,%7}, {%8,%9}, {%0,%1,%2,%3};"
        : "+f"(c[0]), "+f"(c[1]), "+f"(c[2]), "+f"(c[3])
        : "r"(a[0]), "r"(a[1]), "r"(a[2]), "r"(a[3]), "r"(b[0]), "r"(b[1]));
}

__global__ void k_nop() {}

// =====================================================================
// K1 (tf32 mma): partial[seg][b][k][d] = sum_t S[b,t,k] * x[b,t,d]
// grid (3 d-tiles, NSEG, B) x 256 thr (8 warps).
// C[32k x 256d] = S^T[32k x 128t] * x[128t x 256d], 3-term tf32 split.
// A-frag gathers from SsmT[32][132] (bank 4g+tig, conflict-free);
// B-frag gathers from Xsm[16][264]  (bank 8tig+g, conflict-free).
// =====================================================================
__global__ void __launch_bounds__(256) k_project(const float* __restrict__ x,
                                                 const float* __restrict__ S) {
    const int d0  = blockIdx.x * 256;
    const int t0  = blockIdx.y * TSEG;
    const int b   = blockIdx.z;
    const int tid = threadIdx.x;

    __shared__ float SsmT[KSp][132];   // 16.9 KB, S transposed [k][t]
    __shared__ float Xsm[TCH][264];    // 16.9 KB

    const float* xbase = x + ((size_t)b * Tt + t0) * Dd + d0;

    // prefetch x chunk 0: 16 rows x 256 cols = 1024 float4, 4 per thread
    float4 xr[4];
#pragma unroll
    for (int i = 0; i < 4; i++) {
        int idx = tid + i * 256;
        xr[i] = *reinterpret_cast<const float4*>(
            xbase + (size_t)(idx >> 6) * Dd + (idx & 63) * 4);
    }

    // stage S transposed: thread handles t = tid>>1, k-half = (tid&1)*16
    {
        const int tr = tid >> 1;
        const int kh = (tid & 1) * 16;
        const float4* srow = reinterpret_cast<const float4*>(
            S + ((size_t)b * Tt + t0 + tr) * KSp + kh);
#pragma unroll
        for (int j = 0; j < 4; j++) {
            float4 v = srow[j];
            SsmT[kh + j * 4 + 0][tr] = v.x;
            SsmT[kh + j * 4 + 1][tr] = v.y;
            SsmT[kh + j * 4 + 2][tr] = v.z;
            SsmT[kh + j * 4 + 3][tr] = v.w;
        }
    }

    const int wid  = tid >> 5;
    const int lane = tid & 31;
    const int nw   = wid * 32;         // warp's d-offset within 256
    const int g    = lane >> 2;
    const int tig  = lane & 3;

    float c[2][4][4];
#pragma unroll
    for (int i = 0; i < 2; i++)
#pragma unroll
        for (int j = 0; j < 4; j++)
#pragma unroll
            for (int q = 0; q < 4; q++) c[i][j][q] = 0.f;

    for (int ch = 0; ch < CHUNKS; ch++) {
        __syncthreads();
        // commit staged x chunk
#pragma unroll
        for (int i = 0; i < 4; i++) {
            int idx = tid + i * 256;
            *reinterpret_cast<float4*>(&Xsm[idx >> 6][(idx & 63) * 4]) = xr[i];
        }
        __syncthreads();
        // prefetch next chunk (hides behind mma below)
        if (ch + 1 < CHUNKS) {
            const float* nb2 = xbase + (size_t)(ch + 1) * TCH * Dd;
#pragma unroll
            for (int i = 0; i < 4; i++) {
                int idx = tid + i * 256;
                xr[i] = *reinterpret_cast<const float4*>(
                    nb2 + (size_t)(idx >> 6) * Dd + (idx & 63) * 4);
            }
        }
#pragma unroll
        for (int ks = 0; ks < 2; ks++) {
            const int tb = ks * 8;                  // t-base within chunk
            const int tc = ch * TCH + tb;           // t-base within SsmT cols
            uint32_t ahi[2][4], alo[2][4];
#pragma unroll
            for (int mt = 0; mt < 2; mt++) {
                const int mb = mt * 16;
                tf32_split(SsmT[mb + g][tc + tig],         ahi[mt][0], alo[mt][0]);
                tf32_split(SsmT[mb + g + 8][tc + tig],     ahi[mt][1], alo[mt][1]);
                tf32_split(SsmT[mb + g][tc + tig + 4],     ahi[mt][2], alo[mt][2]);
                tf32_split(SsmT[mb + g + 8][tc + tig + 4], ahi[mt][3], alo[mt][3]);
            }
#pragma unroll
            for (int nt = 0; nt < 4; nt++) {
                const int nb = nw + nt * 8;
                uint32_t bhi[2], blo[2];
                tf32_split(Xsm[tb + tig][nb + g],     bhi[0], blo[0]);
                tf32_split(Xsm[tb + tig + 4][nb + g], bhi[1], blo[1]);
#pragma unroll
                for (int mt = 0; mt < 2; mt++) {
                    mma_tf32(c[mt][nt], ahi[mt], bhi);
                    mma_tf32(c[mt][nt], ahi[mt], blo);
                    mma_tf32(c[mt][nt], alo[mt], bhi);
                }
            }
        }
    }

    // write partial: row k = mt*16 + g(+8); col = d0 + nw + nt*8 + tig*2
    float* pb = &g_partial[(((size_t)blockIdx.y * Bb + b) * KSp) * Dd + d0];
#pragma unroll
    for (int mt = 0; mt < 2; mt++) {
        const int r0 = mt * 16 + g;
#pragma unroll
        for (int nt = 0; nt < 4; nt++) {
            const int col = nw + nt * 8 + tig * 2;
            *reinterpret_cast<float2*>(pb + (size_t)r0 * Dd + col) =
                make_float2(c[mt][nt][0], c[mt][nt][1]);
            *reinterpret_cast<float2*>(pb + (size_t)(r0 + 8) * Dd + col) =
                make_float2(c[mt][nt][2], c[mt][nt][3]);
        }
    }
}

// =====================================================================
// K2: xs = sum over 32 segments
// =====================================================================
__global__ void k_reduce() {
    const int i = blockIdx.x * blockDim.x + threadIdx.x;
    const int stride4 = (Bb * KSp * Dd) / 4;
    const float4* p = reinterpret_cast<const float4*>(g_partial);
    float4 s = make_float4(0.f, 0.f, 0.f, 0.f);
#pragma unroll
    for (int seg = 0; seg < NSEG; seg++) {
        float4 v = p[(size_t)seg * stride4 + i];
        s.x += v.x; s.y += v.y; s.z += v.z; s.w += v.w;
    }
    reinterpret_cast<float4*>(g_xs)[i] = s;
}

// =====================================================================
// GEMM template: C[256, N] = A[256, 768] * W[N, 768]^T  (FFMA2, proven)
// =====================================================================
__device__ __forceinline__ void gemm_body(const float* __restrict__ A,
                                          const float* __restrict__ W,
                                          float* __restrict__ C, int N,
                                          int n0, int m0, int tid) {
    const int tn = tid & 15, tm = tid >> 4;
    const int lr = tid >> 3, lc = tid & 7;

    __shared__ float Asm[32][68];
    __shared__ float Bsm[32][68];

    float4 ar[2], br[2];
#pragma unroll
    for (int i = 0; i < 2; i++) {
        ar[i] = *reinterpret_cast<const float4*>(
            &A[(size_t)(m0 + lr + i * 32) * Dd + lc * 4]);
        br[i] = *reinterpret_cast<const float4*>(
            &W[(size_t)(n0 + lr + i * 32) * Dd + lc * 4]);
    }

    u64 acc[4][2];
#pragma unroll
    for (int r = 0; r < 4; r++) { acc[r][0] = 0ull; acc[r][1] = 0ull; }

    for (int d0 = 0; d0 < Dd; d0 += 32) {
#pragma unroll
        for (int i = 0; i < 2; i++) {
            int r = lr + i * 32;
            Asm[lc * 4 + 0][r] = ar[i].x; Asm[lc * 4 + 1][r] = ar[i].y;
            Asm[lc * 4 + 2][r] = ar[i].z; Asm[lc * 4 + 3][r] = ar[i].w;
            Bsm[lc * 4 + 0][r] = br[i].x; Bsm[lc * 4 + 1][r] = br[i].y;
            Bsm[lc * 4 + 2][r] = br[i].z; Bsm[lc * 4 + 3][r] = br[i].w;
        }
        __syncthreads();
        if (d0 + 32 < Dd) {
#pragma unroll
            for (int i = 0; i < 2; i++) {
                ar[i] = *reinterpret_cast<const float4*>(
                    &A[(size_t)(m0 + lr + i * 32) * Dd + d0 + 32 + lc * 4]);
                br[i] = *reinterpret_cast<const float4*>(
                    &W[(size_t)(n0 + lr + i * 32) * Dd + d0 + 32 + lc * 4]);
            }
        }
#pragma unroll
        for (int k = 0; k < 32; k++) {
            float4 av = *reinterpret_cast<const float4*>(&Asm[k][tm * 4]);
            ulonglong2 bv = *reinterpret_cast<const ulonglong2*>(&Bsm[k][tn * 4]);
            u64 a0 = pk2(av.x, av.x), a1 = pk2(av.y, av.y);
            u64 a2 = pk2(av.z, av.z), a3 = pk2(av.w, av.w);
            fma2(acc[0][0], a0, bv.x); fma2(acc[0][1], a0, bv.y);
            fma2(acc[1][0], a1, bv.x); fma2(acc[1][1], a1, bv.y);
            fma2(acc[2][0], a2, bv.x); fma2(acc[2][1], a2, bv.y);
            fma2(acc[3][0], a3, bv.x); fma2(acc[3][1], a3, bv.y);
        }
        __syncthreads();
    }

#pragma unroll
    for (int r = 0; r < 4; r++) {
        ulonglong2 o; o.x = acc[r][0]; o.y = acc[r][1];
        *reinterpret_cast<ulonglong2*>(
            &C[(size_t)(m0 + tm * 4 + r) * N + n0 + tn * 4]) = o;
    }
}

__global__ void __launch_bounds__(256) k_gemm1(const float* __restrict__ W) {
    gemm_body(g_xs, W, g_qkv, D3, blockIdx.x * 64, blockIdx.y * 64, threadIdx.x);
}

__global__ void __launch_bounds__(256) k_gemm2(const float* __restrict__ W) {
    gemm_body(g_vg, W, g_y, Dd, blockIdx.x * 64, blockIdx.y * 64, threadIdx.x);
}

// =====================================================================
// K_fhn: one warp per (b,h,k): dot(q,k) + filter + FHN + scale v -> g_vg
// =====================================================================
__global__ void __launch_bounds__(256) k_fhn(const float* __restrict__ sfilter) {
    const int tid  = threadIdx.x;
    const int lane = tid & 31;
    const int idx  = blockIdx.x * 8 + (tid >> 5);
    const int b    = idx / (Hh * KSp);
    const int r    = idx % (Hh * KSp);
    const int h    = r >> 5;
    const int kidx = r & 31;

    const float* row = &g_qkv[(size_t)(b * KSp + kidx) * D3];
    float2 q  = *reinterpret_cast<const float2*>(row + h * HDd + lane * 2);
    float2 kv = *reinterpret_cast<const float2*>(row + Dd + h * HDd + lane * 2);
    float p = q.x * kv.x + q.y * kv.y;
#pragma unroll
    for (int o = 16; o; o >>= 1) p += __shfl_xor_sync(0xffffffffu, p, o);

    float attn = p * 0.125f;
    float filt = 1.f / (1.f + expf(-sfilter[h * 32 + kidx]));
    attn *= filt;

    float a = fabsf(attn);
    float scale = fmaxf(a, 1e-6f);
    float sn = attn / scale;
    float gate = 1.f / (1.f + expf(-(a - 0.5f) * 10.f));
    float I = sn * (0.1f + 0.9f * gate);
    const float alpha = 1.0f / 12.5f;
    const float denom = 1.0f + alpha * 0.8f;
    float v = 0.f, w = 0.f;
#pragma unroll
    for (int s = 0; s < 2; s++) {
        float dv = v - (v * v * v) * (1.f / 3.f) - w + I;
        float vn = v + dv;
        float wn = (w + (vn + 0.7f) * alpha) / denom;
        v = fminf(fmaxf(vn, -3.f), 3.f);
        w = fminf(fmaxf(wn, -3.f), 3.f);
    }
    float fv = v * scale;

    float2 vs = *reinterpret_cast<const float2*>(row + 2 * Dd + h * HDd + lane * 2);
    *reinterpret_cast<float2*>(&g_vg[(size_t)(b * KSp + kidx) * Dd + h * HDd + lane * 2]) =
        make_float2(fv * vs.x, fv * vs.y);
}

// =====================================================================
// K5: out tile [128t x 128e] = S * y via tf32 mma.sync, 3-term split.
// =====================================================================
__global__ void __launch_bounds__(256, 2) k_expand(const float* __restrict__ S,
                                                   float* __restrict__ out) {
    const int e0  = blockIdx.x * 128;
    const int t0  = blockIdx.y * 128;
    const int b   = blockIdx.z;
    const int tid = threadIdx.x;

    __shared__ float Ssm[128][36];
    __shared__ float Ysm[KSp][136];

    {
        const float4* sg = reinterpret_cast<const float4*>(
            S + ((size_t)b * Tt + t0) * KSp);
#pragma unroll
        for (int i = 0; i < 4; i++) {
            int n = tid + i * 256;
            float4 v = sg[n];
            *reinterpret_cast<float4*>(&Ssm[n >> 3][(n & 7) * 4]) = v;
        }
#pragma unroll
        for (int i = 0; i < 4; i++) {
            int n = tid + i * 256;
            int r = n >> 5, c2 = n & 31;
            *reinterpret_cast<float4*>(&Ysm[r][c2 * 4]) =
                *reinterpret_cast<const float4*>(
                    &g_y[((size_t)b * KSp + r) * Dd + e0 + c2 * 4]);
        }
    }
    __syncthreads();

    const int wid  = tid >> 5;
    const int lane = tid & 31;
    const int tw = (wid >> 1) * 32;
    const int ew = (wid & 1) * 64;
    const int g   = lane >> 2;
    const int tig = lane & 3;

    float c[2][8][4];
#pragma unroll
    for (int i = 0; i < 2; i++)
#pragma unroll
        for (int j = 0; j < 8; j++)
#pragma unroll
            for (int q = 0; q < 4; q++) c[i][j][q] = 0.f;

#pragma unroll
    for (int ks = 0; ks < 4; ks++) {
        const int k0 = ks * 8;
        uint32_t ahi[2][4], alo[2][4];
#pragma unroll
        for (int mt = 0; mt < 2; mt++) {
            const int mb = tw + mt * 16;
            tf32_split(Ssm[mb + g][k0 + tig],        ahi[mt][0], alo[mt][0]);
            tf32_split(Ssm[mb + g + 8][k0 + tig],    ahi[mt][1], alo[mt][1]);
            tf32_split(Ssm[mb + g][k0 + tig + 4],    ahi[mt][2], alo[mt][2]);
            tf32_split(Ssm[mb + g + 8][k0 + tig + 4],ahi[mt][3], alo[mt][3]);
        }
#pragma unroll
        for (int nt = 0; nt < 8; nt++) {
            const int nb = ew + nt * 8;
            uint32_t bhi[2], blo[2];
            tf32_split(Ysm[k0 + tig][nb + g],     bhi[0], blo[0]);
            tf32_split(Ysm[k0 + tig + 4][nb + g], bhi[1], blo[1]);
#pragma unroll
            for (int mt = 0; mt < 2; mt++) {
                mma_tf32(c[mt][nt], ahi[mt], bhi);
                mma_tf32(c[mt][nt], ahi[mt], blo);
                mma_tf32(c[mt][nt], alo[mt], bhi);
            }
        }
    }

#pragma unroll
    for (int mt = 0; mt < 2; mt++) {
        const int rbase = t0 + tw + mt * 16 + g;
#pragma unroll
        for (int nt = 0; nt < 8; nt++) {
            const int col = e0 + ew + nt * 8 + tig * 2;
            *reinterpret_cast<float2*>(
                &out[((size_t)b * Tt + rbase) * Dd + col]) =
                make_float2(c[mt][nt][0], c[mt][nt][1]);
            *reinterpret_cast<float2*>(
                &out[((size_t)b * Tt + rbase + 8) * Dd + col]) =
                make_float2(c[mt][nt][2], c[mt][nt][3]);
        }
    }
}

// =====================================================================
extern "C" void kernel_launch(void* const* d_in, const int* in_sizes, int n_in,
                              void* d_out, int out_size) {
    const float* x       = (const float*)d_in[0];
    const float* S       = (const float*)d_in[1];
    const float* w_qkv   = (const float*)d_in[2];
    const float* w_out   = (const float*)d_in[3];
    const float* sfilter = (const float*)d_in[4];
    float* out = (float*)d_out;

    // 3 nops put the new mma k_project into the profiler's capture slot (#4)
    k_nop<<<1, 32>>>();
    k_nop<<<1, 32>>>();
    k_nop<<<1, 32>>>();
    k_project<<<dim3(3, NSEG, Bb), 256>>>(x, S);
    k_reduce<<<192, 256>>>();
    k_gemm1<<<dim3(D3 / 64, 4), 256>>>(w_qkv);
    k_fhn<<<384, 256>>>(sfilter);
    k_gemm2<<<dim3(Dd / 64, 4), 256>>>(w_out);
    k_expand<<<dim3(6, 32, Bb), 256>>>(S, out);
}

// round 12
// speedup vs baseline: 1.0118x; 1.0118x over previous
#include <cuda_runtime.h>
#include <cstdint>

#define Bb   8
#define Tt   4096
#define Dd   768
#define Hh   12
#define HDd  64
#define KSp  32
#define D3   2304

#define NSEG 32
#define TSEG 128
#define TCH  16
#define CHUNKS (TSEG / TCH)   // 8

typedef unsigned long long u64;

// ---------------- scratch ----------------
__device__ float g_partial[NSEG * Bb * KSp * Dd];   // 25.2 MB (L2-resident)
__device__ float g_xs[Bb * KSp * Dd];
__device__ float g_qkv[Bb * KSp * D3];
__device__ float g_vg[Bb * KSp * Dd];
__device__ float g_y[Bb * KSp * Dd];

// ---------------- packed f32x2 ----------------
__device__ __forceinline__ u64 pk2(float lo, float hi) {
    u64 r;
    asm("mov.b64 %0, {%1, %2};" : "=l"(r) : "f"(lo), "f"(hi));
    return r;
}
__device__ __forceinline__ void fma2(u64& d, u64 a, u64 b) {
    asm("fma.rn.f32x2 %0, %1, %2, %0;" : "+l"(d) : "l"(a), "l"(b));
}

// ---------------- tf32 helpers (k_expand, R8-verified) ----------------
__device__ __forceinline__ void tf32_split(float x, uint32_t& hi, uint32_t& lo) {
    uint32_t h;
    asm("cvt.rna.tf32.f32 %0, %1;" : "=r"(h) : "f"(x));
    float r = x - __uint_as_float(h);
    asm("cvt.rna.tf32.f32 %0, %1;" : "=r"(lo) : "f"(r));
    hi = h;
}
__device__ __forceinline__ void mma_tf32(float* c, const uint32_t* a,
                                         const uint32_t* b) {
    asm("mma.sync.aligned.m16n8k8.row.col.f32.tf32.tf32.f32 "
        "{%0,%1,%2,%3}, {%4,%5,%6,%7}, {%8,%9}, {%0,%1,%2,%3};"
        : "+f"(c[0]), "+f"(c[1]), "+f"(c[2]), "+f"(c[3])
        : "r"(a[0]), "r"(a[1]), "r"(a[2]), "r"(a[3]), "r"(b[0]), "r"(b[1]));
}

// ---------------- bf16 helpers ----------------
// pack two f32 -> bf16x2 {high=bf16(h), low=bf16(l)}
__device__ __forceinline__ uint32_t bfpack(float h, float l) {
    uint32_t d;
    asm("cvt.rn.bf16x2.f32 %0, %1, %2;" : "=r"(d) : "f"(h), "f"(l));
    return d;
}
// split pair (x0 -> low, x1 -> high) into hi/lo bf16x2 words
__device__ __forceinline__ void bf_split2(float x0, float x1,
                                          uint32_t& hi, uint32_t& lo) {
    hi = bfpack(x1, x0);
    float l0 = __uint_as_float(hi << 16);
    float h0 = __uint_as_float(hi & 0xffff0000u);
    lo = bfpack(x1 - h0, x0 - l0);
}
__device__ __forceinline__ void mma_bf16(float* c, const uint32_t* a,
                                         const uint32_t* b) {
    asm("mma.sync.aligned.m16n8k16.row.col.f32.bf16.bf16.f32 "
        "{%0,%1,%2,%3}, {%4,%5,%6,%7}, {%8,%9}, {%0,%1,%2,%3};"
        : "+f"(c[0]), "+f"(c[1]), "+f"(c[2]), "+f"(c[3])
        : "r"(a[0]), "r"(a[1]), "r"(a[2]), "r"(a[3]), "r"(b[0]), "r"(b[1]));
}

__global__ void k_nop() {}

// =====================================================================
// K1 (bf16 m16n8k16, 3-term): partial[seg][b][k][d] = sum_t S^T x
// grid (3 d-tiles, NSEG, B) x 256 thr (8 warps).
// S split/packed ONCE in prologue (Ap arrays, t-pairs along k);
// x split at staging time (Xp arrays). Mainloop = pure LDS + mma.
// =====================================================================
__global__ void __launch_bounds__(256) k_project(const float* __restrict__ x,
                                                 const float* __restrict__ S) {
    const int d0  = blockIdx.x * 256;
    const int t0  = blockIdx.y * TSEG;
    const int b   = blockIdx.z;
    const int tid = threadIdx.x;

    __shared__ uint32_t Ap_hi[KSp][68];   // 8.7 KB  S^T pairs, bf16x2
    __shared__ uint32_t Ap_lo[KSp][68];   // 8.7 KB
    __shared__ uint32_t Xp_hi[8][264];    // 8.45 KB x k-pairs, bf16x2
    __shared__ uint32_t Xp_lo[8][264];    // 8.45 KB   (34.3 KB total)

    // ---- staging map: thread owns k-pair kk, 8 d-cols c..c+7 ----
    const int kk = tid >> 5;          // 0..7
    const int c  = (tid & 31) * 8;    // 0..248

    const float* xbase = x + ((size_t)b * Tt + t0) * Dd + d0;

    // prefetch chunk 0 rows (2kk, 2kk+1)
    float4 xr[4];
    {
        const float* r0 = xbase + (size_t)(2 * kk) * Dd + c;
        xr[0] = *reinterpret_cast<const float4*>(r0);
        xr[1] = *reinterpret_cast<const float4*>(r0 + 4);
        xr[2] = *reinterpret_cast<const float4*>(r0 + Dd);
        xr[3] = *reinterpret_cast<const float4*>(r0 + Dd + 4);
    }

    // ---- S prologue: split+pack whole 128t x 32k tile once ----
    {
        const int tp = tid & 63;      // t-pair 0..63
        const int mh = tid >> 6;      // 0..3 -> 8 m-rows each
        const float* s0 = S + ((size_t)b * Tt + t0 + 2 * tp) * KSp + mh * 8;
        float4 A0 = *reinterpret_cast<const float4*>(s0);
        float4 A0b = *reinterpret_cast<const float4*>(s0 + 4);
        float4 A1 = *reinterpret_cast<const float4*>(s0 + KSp);
        float4 A1b = *reinterpret_cast<const float4*>(s0 + KSp + 4);
        float v0[8] = {A0.x, A0.y, A0.z, A0.w, A0b.x, A0b.y, A0b.z, A0b.w};
        float v1[8] = {A1.x, A1.y, A1.z, A1.w, A1b.x, A1b.y, A1b.z, A1b.w};
#pragma unroll
        for (int j = 0; j < 8; j++) {
            uint32_t h, l;
            bf_split2(v0[j], v1[j], h, l);   // low=t even
            Ap_hi[mh * 8 + j][tp] = h;
            Ap_lo[mh * 8 + j][tp] = l;
        }
    }

    const int wid  = tid >> 5;
    const int lane = tid & 31;
    const int nw   = wid * 32;
    const int g    = lane >> 2;
    const int tig  = lane & 3;

    float cacc[2][4][4];
#pragma unroll
    for (int i = 0; i < 2; i++)
#pragma unroll
        for (int j = 0; j < 4; j++)
#pragma unroll
            for (int q = 0; q < 4; q++) cacc[i][j][q] = 0.f;

    for (int ch = 0; ch < CHUNKS; ch++) {
        __syncthreads();
        // split staged x rows (each element exactly once) and store packed
        {
            float x0[8] = {xr[0].x, xr[0].y, xr[0].z, xr[0].w,
                           xr[1].x, xr[1].y, xr[1].z, xr[1].w};
            float x1[8] = {xr[2].x, xr[2].y, xr[2].z, xr[2].w,
                           xr[3].x, xr[3].y, xr[3].z, xr[3].w};
            uint32_t hi[8], lo[8];
#pragma unroll
            for (int j = 0; j < 8; j++) bf_split2(x0[j], x1[j], hi[j], lo[j]);
            *reinterpret_cast<uint4*>(&Xp_hi[kk][c]) =
                make_uint4(hi[0], hi[1], hi[2], hi[3]);
            *reinterpret_cast<uint4*>(&Xp_hi[kk][c + 4]) =
                make_uint4(hi[4], hi[5], hi[6], hi[7]);
            *reinterpret_cast<uint4*>(&Xp_lo[kk][c]) =
                make_uint4(lo[0], lo[1], lo[2], lo[3]);
            *reinterpret_cast<uint4*>(&Xp_lo[kk][c + 4]) =
                make_uint4(lo[4], lo[5], lo[6], lo[7]);
        }
        __syncthreads();
        // prefetch next chunk (hides behind mma)
        if (ch + 1 < CHUNKS) {
            const float* r0 = xbase + (size_t)((ch + 1) * TCH + 2 * kk) * Dd + c;
            xr[0] = *reinterpret_cast<const float4*>(r0);
            xr[1] = *reinterpret_cast<const float4*>(r0 + 4);
            xr[2] = *reinterpret_cast<const float4*>(r0 + Dd);
            xr[3] = *reinterpret_cast<const float4*>(r0 + Dd + 4);
        }
        // one K=16 mma step covers the whole chunk
        const int tc2 = ch * 8;       // t-pair base
        uint32_t ahi[2][4], alo[2][4];
#pragma unroll
        for (int mt = 0; mt < 2; mt++) {
            const int mb = mt * 16;
            ahi[mt][0] = Ap_hi[mb + g][tc2 + tig];
            ahi[mt][1] = Ap_hi[mb + g + 8][tc2 + tig];
            ahi[mt][2] = Ap_hi[mb + g][tc2 + tig + 4];
            ahi[mt][3] = Ap_hi[mb + g + 8][tc2 + tig + 4];
            alo[mt][0] = Ap_lo[mb + g][tc2 + tig];
            alo[mt][1] = Ap_lo[mb + g + 8][tc2 + tig];
            alo[mt][2] = Ap_lo[mb + g][tc2 + tig + 4];
            alo[mt][3] = Ap_lo[mb + g + 8][tc2 + tig + 4];
        }
#pragma unroll
        for (int nt = 0; nt < 4; nt++) {
            const int nb = nw + nt * 8;
            uint32_t bhi[2], blo[2];
            bhi[0] = Xp_hi[tig][nb + g];
            bhi[1] = Xp_hi[tig + 4][nb + g];
            blo[0] = Xp_lo[tig][nb + g];
            blo[1] = Xp_lo[tig + 4][nb + g];
#pragma unroll
            for (int mt = 0; mt < 2; mt++) {
                mma_bf16(cacc[mt][nt], ahi[mt], bhi);
                mma_bf16(cacc[mt][nt], ahi[mt], blo);
                mma_bf16(cacc[mt][nt], alo[mt], bhi);
            }
        }
    }

    // write partial: row k = mt*16 + g(+8); col = nw + nt*8 + 2*tig(+1)
    float* pb = &g_partial[(((size_t)blockIdx.y * Bb + b) * KSp) * Dd + d0];
#pragma unroll
    for (int mt = 0; mt < 2; mt++) {
        const int r0 = mt * 16 + g;
#pragma unroll
        for (int nt = 0; nt < 4; nt++) {
            const int col = nw + nt * 8 + tig * 2;
            *reinterpret_cast<float2*>(pb + (size_t)r0 * Dd + col) =
                make_float2(cacc[mt][nt][0], cacc[mt][nt][1]);
            *reinterpret_cast<float2*>(pb + (size_t)(r0 + 8) * Dd + col) =
                make_float2(cacc[mt][nt][2], cacc[mt][nt][3]);
        }
    }
}

// =====================================================================
// K2: xs = sum over 32 segments
// =====================================================================
__global__ void k_reduce() {
    const int i = blockIdx.x * blockDim.x + threadIdx.x;
    const int stride4 = (Bb * KSp * Dd) / 4;
    const float4* p = reinterpret_cast<const float4*>(g_partial);
    float4 s = make_float4(0.f, 0.f, 0.f, 0.f);
#pragma unroll
    for (int seg = 0; seg < NSEG; seg++) {
        float4 v = p[(size_t)seg * stride4 + i];
        s.x += v.x; s.y += v.y; s.z += v.z; s.w += v.w;
    }
    reinterpret_cast<float4*>(g_xs)[i] = s;
}

// =====================================================================
// GEMM template: C[256, N] = A[256, 768] * W[N, 768]^T  (FFMA2, proven)
// =====================================================================
__device__ __forceinline__ void gemm_body(const float* __restrict__ A,
                                          const float* __restrict__ W,
                                          float* __restrict__ C, int N,
                                          int n0, int m0, int tid) {
    const int tn = tid & 15, tm = tid >> 4;
    const int lr = tid >> 3, lc = tid & 7;

    __shared__ float Asm[32][68];
    __shared__ float Bsm[32][68];

    float4 ar[2], br[2];
#pragma unroll
    for (int i = 0; i < 2; i++) {
        ar[i] = *reinterpret_cast<const float4*>(
            &A[(size_t)(m0 + lr + i * 32) * Dd + lc * 4]);
        br[i] = *reinterpret_cast<const float4*>(
            &W[(size_t)(n0 + lr + i * 32) * Dd + lc * 4]);
    }

    u64 acc[4][2];
#pragma unroll
    for (int r = 0; r < 4; r++) { acc[r][0] = 0ull; acc[r][1] = 0ull; }

    for (int d0 = 0; d0 < Dd; d0 += 32) {
#pragma unroll
        for (int i = 0; i < 2; i++) {
            int r = lr + i * 32;
            Asm[lc * 4 + 0][r] = ar[i].x; Asm[lc * 4 + 1][r] = ar[i].y;
            Asm[lc * 4 + 2][r] = ar[i].z; Asm[lc * 4 + 3][r] = ar[i].w;
            Bsm[lc * 4 + 0][r] = br[i].x; Bsm[lc * 4 + 1][r] = br[i].y;
            Bsm[lc * 4 + 2][r] = br[i].z; Bsm[lc * 4 + 3][r] = br[i].w;
        }
        __syncthreads();
        if (d0 + 32 < Dd) {
#pragma unroll
            for (int i = 0; i < 2; i++) {
                ar[i] = *reinterpret_cast<const float4*>(
                    &A[(size_t)(m0 + lr + i * 32) * Dd + d0 + 32 + lc * 4]);
                br[i] = *reinterpret_cast<const float4*>(
                    &W[(size_t)(n0 + lr + i * 32) * Dd + d0 + 32 + lc * 4]);
            }
        }
#pragma unroll
        for (int k = 0; k < 32; k++) {
            float4 av = *reinterpret_cast<const float4*>(&Asm[k][tm * 4]);
            ulonglong2 bv = *reinterpret_cast<const ulonglong2*>(&Bsm[k][tn * 4]);
            u64 a0 = pk2(av.x, av.x), a1 = pk2(av.y, av.y);
            u64 a2 = pk2(av.z, av.z), a3 = pk2(av.w, av.w);
            fma2(acc[0][0], a0, bv.x); fma2(acc[0][1], a0, bv.y);
            fma2(acc[1][0], a1, bv.x); fma2(acc[1][1], a1, bv.y);
            fma2(acc[2][0], a2, bv.x); fma2(acc[2][1], a2, bv.y);
            fma2(acc[3][0], a3, bv.x); fma2(acc[3][1], a3, bv.y);
        }
        __syncthreads();
    }

#pragma unroll
    for (int r = 0; r < 4; r++) {
        ulonglong2 o; o.x = acc[r][0]; o.y = acc[r][1];
        *reinterpret_cast<ulonglong2*>(
            &C[(size_t)(m0 + tm * 4 + r) * N + n0 + tn * 4]) = o;
    }
}

__global__ void __launch_bounds__(256) k_gemm1(const float* __restrict__ W) {
    gemm_body(g_xs, W, g_qkv, D3, blockIdx.x * 64, blockIdx.y * 64, threadIdx.x);
}

__global__ void __launch_bounds__(256) k_gemm2(const float* __restrict__ W) {
    gemm_body(g_vg, W, g_y, Dd, blockIdx.x * 64, blockIdx.y * 64, threadIdx.x);
}

// =====================================================================
// K_fhn: one warp per (b,h,k): dot(q,k) + filter + FHN + scale v -> g_vg
// =====================================================================
__global__ void __launch_bounds__(256) k_fhn(const float* __restrict__ sfilter) {
    const int tid  = threadIdx.x;
    const int lane = tid & 31;
    const int idx  = blockIdx.x * 8 + (tid >> 5);
    const int b    = idx / (Hh * KSp);
    const int r    = idx % (Hh * KSp);
    const int h    = r >> 5;
    const int kidx = r & 31;

    const float* row = &g_qkv[(size_t)(b * KSp + kidx) * D3];
    float2 q  = *reinterpret_cast<const float2*>(row + h * HDd + lane * 2);
    float2 kv = *reinterpret_cast<const float2*>(row + Dd + h * HDd + lane * 2);
    float p = q.x * kv.x + q.y * kv.y;
#pragma unroll
    for (int o = 16; o; o >>= 1) p += __shfl_xor_sync(0xffffffffu, p, o);

    float attn = p * 0.125f;
    float filt = 1.f / (1.f + expf(-sfilter[h * 32 + kidx]));
    attn *= filt;

    float a = fabsf(attn);
    float scale = fmaxf(a, 1e-6f);
    float sn = attn / scale;
    float gate = 1.f / (1.f + expf(-(a - 0.5f) * 10.f));
    float I = sn * (0.1f + 0.9f * gate);
    const float alpha = 1.0f / 12.5f;
    const float denom = 1.0f + alpha * 0.8f;
    float v = 0.f, w = 0.f;
#pragma unroll
    for (int s = 0; s < 2; s++) {
        float dv = v - (v * v * v) * (1.f / 3.f) - w + I;
        float vn = v + dv;
        float wn = (w + (vn + 0.7f) * alpha) / denom;
        v = fminf(fmaxf(vn, -3.f), 3.f);
        w = fminf(fmaxf(wn, -3.f), 3.f);
    }
    float fv = v * scale;

    float2 vs = *reinterpret_cast<const float2*>(row + 2 * Dd + h * HDd + lane * 2);
    *reinterpret_cast<float2*>(&g_vg[(size_t)(b * KSp + kidx) * Dd + h * HDd + lane * 2]) =
        make_float2(fv * vs.x, fv * vs.y);
}

// =====================================================================
// K5: out tile [128t x 128e] = S * y via tf32 mma.sync, 3-term split.
// =====================================================================
__global__ void __launch_bounds__(256, 2) k_expand(const float* __restrict__ S,
                                                   float* __restrict__ out) {
    const int e0  = blockIdx.x * 128;
    const int t0  = blockIdx.y * 128;
    const int b   = blockIdx.z;
    const int tid = threadIdx.x;

    __shared__ float Ssm[128][36];
    __shared__ float Ysm[KSp][136];

    {
        const float4* sg = reinterpret_cast<const float4*>(
            S + ((size_t)b * Tt + t0) * KSp);
#pragma unroll
        for (int i = 0; i < 4; i++) {
            int n = tid + i * 256;
            float4 v = sg[n];
            *reinterpret_cast<float4*>(&Ssm[n >> 3][(n & 7) * 4]) = v;
        }
#pragma unroll
        for (int i = 0; i < 4; i++) {
            int n = tid + i * 256;
            int r = n >> 5, c2 = n & 31;
            *reinterpret_cast<float4*>(&Ysm[r][c2 * 4]) =
                *reinterpret_cast<const float4*>(
                    &g_y[((size_t)b * KSp + r) * Dd + e0 + c2 * 4]);
        }
    }
    __syncthreads();

    const int wid  = tid >> 5;
    const int lane = tid & 31;
    const int tw = (wid >> 1) * 32;
    const int ew = (wid & 1) * 64;
    const int g   = lane >> 2;
    const int tig = lane & 3;

    float c[2][8][4];
#pragma unroll
    for (int i = 0; i < 2; i++)
#pragma unroll
        for (int j = 0; j < 8; j++)
#pragma unroll
            for (int q = 0; q < 4; q++) c[i][j][q] = 0.f;

#pragma unroll
    for (int ks = 0; ks < 4; ks++) {
        const int k0 = ks * 8;
        uint32_t ahi[2][4], alo[2][4];
#pragma unroll
        for (int mt = 0; mt < 2; mt++) {
            const int mb = tw + mt * 16;
            tf32_split(Ssm[mb + g][k0 + tig],        ahi[mt][0], alo[mt][0]);
            tf32_split(Ssm[mb + g + 8][k0 + tig],    ahi[mt][1], alo[mt][1]);
            tf32_split(Ssm[mb + g][k0 + tig + 4],    ahi[mt][2], alo[mt][2]);
            tf32_split(Ssm[mb + g + 8][k0 + tig + 4],ahi[mt][3], alo[mt][3]);
        }
#pragma unroll
        for (int nt = 0; nt < 8; nt++) {
            const int nb = ew + nt * 8;
            uint32_t bhi[2], blo[2];
            tf32_split(Ysm[k0 + tig][nb + g],     bhi[0], blo[0]);
            tf32_split(Ysm[k0 + tig + 4][nb + g], bhi[1], blo[1]);
#pragma unroll
            for (int mt = 0; mt < 2; mt++) {
                mma_tf32(c[mt][nt], ahi[mt], bhi);
                mma_tf32(c[mt][nt], ahi[mt], blo);
                mma_tf32(c[mt][nt], alo[mt], bhi);
            }
        }
    }

#pragma unroll
    for (int mt = 0; mt < 2; mt++) {
        const int rbase = t0 + tw + mt * 16 + g;
#pragma unroll
        for (int nt = 0; nt < 8; nt++) {
            const int col = e0 + ew + nt * 8 + tig * 2;
            *reinterpret_cast<float2*>(
                &out[((size_t)b * Tt + rbase) * Dd + col]) =
                make_float2(c[mt][nt][0], c[mt][nt][1]);
            *reinterpret_cast<float2*>(
                &out[((size_t)b * Tt + rbase + 8) * Dd + col]) =
                make_float2(c[mt][nt][2], c[mt][nt][3]);
        }
    }
}

// =====================================================================
extern "C" void kernel_launch(void* const* d_in, const int* in_sizes, int n_in,
                              void* d_out, int out_size) {
    const float* x       = (const float*)d_in[0];
    const float* S       = (const float*)d_in[1];
    const float* w_qkv   = (const float*)d_in[2];
    const float* w_out   = (const float*)d_in[3];
    const float* sfilter = (const float*)d_in[4];
    float* out = (float*)d_out;

    // 3 nops keep k_project in the profiler's capture slot (#4)
    k_nop<<<1, 32>>>();
    k_nop<<<1, 32>>>();
    k_nop<<<1, 32>>>();
    k_project<<<dim3(3, NSEG, Bb), 256>>>(x, S);
    k_reduce<<<192, 256>>>();
    k_gemm1<<<dim3(D3 / 64, 4), 256>>>(w_qkv);
    k_fhn<<<384, 256>>>(sfilter);
    k_gemm2<<<dim3(Dd / 64, 4), 256>>>(w_out);
    k_expand<<<dim3(6, 32, Bb), 256>>>(S, out);
}

// round 13
// speedup vs baseline: 1.0610x; 1.0487x over previous
#include <cuda_runtime.h>
#include <cstdint>

#define Bb   8
#define Tt   4096
#define Dd   768
#define Hh   12
#define HDd  64
#define KSp  32
#define D3   2304

#define NSEG 32
#define TSEG 128
#define TCH  16
#define CHUNKS (TSEG / TCH)   // 8

typedef unsigned long long u64;

// ---------------- scratch ----------------
__device__ float g_partial[NSEG * Bb * KSp * Dd];   // 25.2 MB (L2-resident)
__device__ float g_xs[Bb * KSp * Dd];
__device__ float g_qkv[Bb * KSp * D3];
__device__ float g_vg[Bb * KSp * Dd];
__device__ float g_y[Bb * KSp * Dd];

// ---------------- packed f32x2 ----------------
__device__ __forceinline__ u64 pk2(float lo, float hi) {
    u64 r;
    asm("mov.b64 %0, {%1, %2};" : "=l"(r) : "f"(lo), "f"(hi));
    return r;
}
__device__ __forceinline__ void fma2(u64& d, u64 a, u64 b) {
    asm("fma.rn.f32x2 %0, %1, %2, %0;" : "+l"(d) : "l"(a), "l"(b));
}

// ---------------- bf16 helpers (R12-verified in k_project) ----------------
__device__ __forceinline__ uint32_t bfpack(float h, float l) {
    uint32_t d;
    asm("cvt.rn.bf16x2.f32 %0, %1, %2;" : "=r"(d) : "f"(h), "f"(l));
    return d;
}
// split pair (x0 -> low half, x1 -> high half) into hi/lo bf16x2 words
__device__ __forceinline__ void bf_split2(float x0, float x1,
                                          uint32_t& hi, uint32_t& lo) {
    hi = bfpack(x1, x0);
    float l0 = __uint_as_float(hi << 16);
    float h0 = __uint_as_float(hi & 0xffff0000u);
    lo = bfpack(x1 - h0, x0 - l0);
}
__device__ __forceinline__ void mma_bf16(float* c, const uint32_t* a,
                                         const uint32_t* b) {
    asm("mma.sync.aligned.m16n8k16.row.col.f32.bf16.bf16.f32 "
        "{%0,%1,%2,%3}, {%4,%5,%6,%7}, {%8,%9}, {%0,%1,%2,%3};"
        : "+f"(c[0]), "+f"(c[1]), "+f"(c[2]), "+f"(c[3])
        : "r"(a[0]), "r"(a[1]), "r"(a[2]), "r"(a[3]), "r"(b[0]), "r"(b[1]));
}

__global__ void k_nop() {}

// =====================================================================
// K1 (bf16 m16n8k16, 3-term): partial[seg][b][k][d] = sum_t S^T x
// (R12 kernel, measured 37.0us, unchanged)
// =====================================================================
__global__ void __launch_bounds__(256) k_project(const float* __restrict__ x,
                                                 const float* __restrict__ S) {
    const int d0  = blockIdx.x * 256;
    const int t0  = blockIdx.y * TSEG;
    const int b   = blockIdx.z;
    const int tid = threadIdx.x;

    __shared__ uint32_t Ap_hi[KSp][68];
    __shared__ uint32_t Ap_lo[KSp][68];
    __shared__ uint32_t Xp_hi[8][264];
    __shared__ uint32_t Xp_lo[8][264];

    const int kk = tid >> 5;
    const int c  = (tid & 31) * 8;

    const float* xbase = x + ((size_t)b * Tt + t0) * Dd + d0;

    float4 xr[4];
    {
        const float* r0 = xbase + (size_t)(2 * kk) * Dd + c;
        xr[0] = *reinterpret_cast<const float4*>(r0);
        xr[1] = *reinterpret_cast<const float4*>(r0 + 4);
        xr[2] = *reinterpret_cast<const float4*>(r0 + Dd);
        xr[3] = *reinterpret_cast<const float4*>(r0 + Dd + 4);
    }

    {
        const int tp = tid & 63;
        const int mh = tid >> 6;
        const float* s0 = S + ((size_t)b * Tt + t0 + 2 * tp) * KSp + mh * 8;
        float4 A0 = *reinterpret_cast<const float4*>(s0);
        float4 A0b = *reinterpret_cast<const float4*>(s0 + 4);
        float4 A1 = *reinterpret_cast<const float4*>(s0 + KSp);
        float4 A1b = *reinterpret_cast<const float4*>(s0 + KSp + 4);
        float v0[8] = {A0.x, A0.y, A0.z, A0.w, A0b.x, A0b.y, A0b.z, A0b.w};
        float v1[8] = {A1.x, A1.y, A1.z, A1.w, A1b.x, A1b.y, A1b.z, A1b.w};
#pragma unroll
        for (int j = 0; j < 8; j++) {
            uint32_t h, l;
            bf_split2(v0[j], v1[j], h, l);
            Ap_hi[mh * 8 + j][tp] = h;
            Ap_lo[mh * 8 + j][tp] = l;
        }
    }

    const int wid  = tid >> 5;
    const int lane = tid & 31;
    const int nw   = wid * 32;
    const int g    = lane >> 2;
    const int tig  = lane & 3;

    float cacc[2][4][4];
#pragma unroll
    for (int i = 0; i < 2; i++)
#pragma unroll
        for (int j = 0; j < 4; j++)
#pragma unroll
            for (int q = 0; q < 4; q++) cacc[i][j][q] = 0.f;

    for (int ch = 0; ch < CHUNKS; ch++) {
        __syncthreads();
        {
            float x0[8] = {xr[0].x, xr[0].y, xr[0].z, xr[0].w,
                           xr[1].x, xr[1].y, xr[1].z, xr[1].w};
            float x1[8] = {xr[2].x, xr[2].y, xr[2].z, xr[2].w,
                           xr[3].x, xr[3].y, xr[3].z, xr[3].w};
            uint32_t hi[8], lo[8];
#pragma unroll
            for (int j = 0; j < 8; j++) bf_split2(x0[j], x1[j], hi[j], lo[j]);
            *reinterpret_cast<uint4*>(&Xp_hi[kk][c]) =
                make_uint4(hi[0], hi[1], hi[2], hi[3]);
            *reinterpret_cast<uint4*>(&Xp_hi[kk][c + 4]) =
                make_uint4(hi[4], hi[5], hi[6], hi[7]);
            *reinterpret_cast<uint4*>(&Xp_lo[kk][c]) =
                make_uint4(lo[0], lo[1], lo[2], lo[3]);
            *reinterpret_cast<uint4*>(&Xp_lo[kk][c + 4]) =
                make_uint4(lo[4], lo[5], lo[6], lo[7]);
        }
        __syncthreads();
        if (ch + 1 < CHUNKS) {
            const float* r0 = xbase + (size_t)((ch + 1) * TCH + 2 * kk) * Dd + c;
            xr[0] = *reinterpret_cast<const float4*>(r0);
            xr[1] = *reinterpret_cast<const float4*>(r0 + 4);
            xr[2] = *reinterpret_cast<const float4*>(r0 + Dd);
            xr[3] = *reinterpret_cast<const float4*>(r0 + Dd + 4);
        }
        const int tc2 = ch * 8;
        uint32_t ahi[2][4], alo[2][4];
#pragma unroll
        for (int mt = 0; mt < 2; mt++) {
            const int mb = mt * 16;
            ahi[mt][0] = Ap_hi[mb + g][tc2 + tig];
            ahi[mt][1] = Ap_hi[mb + g + 8][tc2 + tig];
            ahi[mt][2] = Ap_hi[mb + g][tc2 + tig + 4];
            ahi[mt][3] = Ap_hi[mb + g + 8][tc2 + tig + 4];
            alo[mt][0] = Ap_lo[mb + g][tc2 + tig];
            alo[mt][1] = Ap_lo[mb + g + 8][tc2 + tig];
            alo[mt][2] = Ap_lo[mb + g][tc2 + tig + 4];
            alo[mt][3] = Ap_lo[mb + g + 8][tc2 + tig + 4];
        }
#pragma unroll
        for (int nt = 0; nt < 4; nt++) {
            const int nb = nw + nt * 8;
            uint32_t bhi[2], blo[2];
            bhi[0] = Xp_hi[tig][nb + g];
            bhi[1] = Xp_hi[tig + 4][nb + g];
            blo[0] = Xp_lo[tig][nb + g];
            blo[1] = Xp_lo[tig + 4][nb + g];
#pragma unroll
            for (int mt = 0; mt < 2; mt++) {
                mma_bf16(cacc[mt][nt], ahi[mt], bhi);
                mma_bf16(cacc[mt][nt], ahi[mt], blo);
                mma_bf16(cacc[mt][nt], alo[mt], bhi);
            }
        }
    }

    float* pb = &g_partial[(((size_t)blockIdx.y * Bb + b) * KSp) * Dd + d0];
#pragma unroll
    for (int mt = 0; mt < 2; mt++) {
        const int r0 = mt * 16 + g;
#pragma unroll
        for (int nt = 0; nt < 4; nt++) {
            const int col = nw + nt * 8 + tig * 2;
            *reinterpret_cast<float2*>(pb + (size_t)r0 * Dd + col) =
                make_float2(cacc[mt][nt][0], cacc[mt][nt][1]);
            *reinterpret_cast<float2*>(pb + (size_t)(r0 + 8) * Dd + col) =
                make_float2(cacc[mt][nt][2], cacc[mt][nt][3]);
        }
    }
}

// =====================================================================
// K2: xs = sum over 32 segments
// =====================================================================
__global__ void k_reduce() {
    const int i = blockIdx.x * blockDim.x + threadIdx.x;
    const int stride4 = (Bb * KSp * Dd) / 4;
    const float4* p = reinterpret_cast<const float4*>(g_partial);
    float4 s = make_float4(0.f, 0.f, 0.f, 0.f);
#pragma unroll
    for (int seg = 0; seg < NSEG; seg++) {
        float4 v = p[(size_t)seg * stride4 + i];
        s.x += v.x; s.y += v.y; s.z += v.z; s.w += v.w;
    }
    reinterpret_cast<float4*>(g_xs)[i] = s;
}

// =====================================================================
// GEMM template: C[256, N] = A[256, 768] * W[N, 768]^T  (FFMA2, proven)
// =====================================================================
__device__ __forceinline__ void gemm_body(const float* __restrict__ A,
                                          const float* __restrict__ W,
                                          float* __restrict__ C, int N,
                                          int n0, int m0, int tid) {
    const int tn = tid & 15, tm = tid >> 4;
    const int lr = tid >> 3, lc = tid & 7;

    __shared__ float Asm[32][68];
    __shared__ float Bsm[32][68];

    float4 ar[2], br[2];
#pragma unroll
    for (int i = 0; i < 2; i++) {
        ar[i] = *reinterpret_cast<const float4*>(
            &A[(size_t)(m0 + lr + i * 32) * Dd + lc * 4]);
        br[i] = *reinterpret_cast<const float4*>(
            &W[(size_t)(n0 + lr + i * 32) * Dd + lc * 4]);
    }

    u64 acc[4][2];
#pragma unroll
    for (int r = 0; r < 4; r++) { acc[r][0] = 0ull; acc[r][1] = 0ull; }

    for (int d0 = 0; d0 < Dd; d0 += 32) {
#pragma unroll
        for (int i = 0; i < 2; i++) {
            int r = lr + i * 32;
            Asm[lc * 4 + 0][r] = ar[i].x; Asm[lc * 4 + 1][r] = ar[i].y;
            Asm[lc * 4 + 2][r] = ar[i].z; Asm[lc * 4 + 3][r] = ar[i].w;
            Bsm[lc * 4 + 0][r] = br[i].x; Bsm[lc * 4 + 1][r] = br[i].y;
            Bsm[lc * 4 + 2][r] = br[i].z; Bsm[lc * 4 + 3][r] = br[i].w;
        }
        __syncthreads();
        if (d0 + 32 < Dd) {
#pragma unroll
            for (int i = 0; i < 2; i++) {
                ar[i] = *reinterpret_cast<const float4*>(
                    &A[(size_t)(m0 + lr + i * 32) * Dd + d0 + 32 + lc * 4]);
                br[i] = *reinterpret_cast<const float4*>(
                    &W[(size_t)(n0 + lr + i * 32) * Dd + d0 + 32 + lc * 4]);
            }
        }
#pragma unroll
        for (int k = 0; k < 32; k++) {
            float4 av = *reinterpret_cast<const float4*>(&Asm[k][tm * 4]);
            ulonglong2 bv = *reinterpret_cast<const ulonglong2*>(&Bsm[k][tn * 4]);
            u64 a0 = pk2(av.x, av.x), a1 = pk2(av.y, av.y);
            u64 a2 = pk2(av.z, av.z), a3 = pk2(av.w, av.w);
            fma2(acc[0][0], a0, bv.x); fma2(acc[0][1], a0, bv.y);
            fma2(acc[1][0], a1, bv.x); fma2(acc[1][1], a1, bv.y);
            fma2(acc[2][0], a2, bv.x); fma2(acc[2][1], a2, bv.y);
            fma2(acc[3][0], a3, bv.x); fma2(acc[3][1], a3, bv.y);
        }
        __syncthreads();
    }

#pragma unroll
    for (int r = 0; r < 4; r++) {
        ulonglong2 o; o.x = acc[r][0]; o.y = acc[r][1];
        *reinterpret_cast<ulonglong2*>(
            &C[(size_t)(m0 + tm * 4 + r) * N + n0 + tn * 4]) = o;
    }
}

__global__ void __launch_bounds__(256) k_gemm1(const float* __restrict__ W) {
    gemm_body(g_xs, W, g_qkv, D3, blockIdx.x * 64, blockIdx.y * 64, threadIdx.x);
}

__global__ void __launch_bounds__(256) k_gemm2(const float* __restrict__ W) {
    gemm_body(g_vg, W, g_y, Dd, blockIdx.x * 64, blockIdx.y * 64, threadIdx.x);
}

// =====================================================================
// K_fhn: one warp per (b,h,k)
// =====================================================================
__global__ void __launch_bounds__(256) k_fhn(const float* __restrict__ sfilter) {
    const int tid  = threadIdx.x;
    const int lane = tid & 31;
    const int idx  = blockIdx.x * 8 + (tid >> 5);
    const int b    = idx / (Hh * KSp);
    const int r    = idx % (Hh * KSp);
    const int h    = r >> 5;
    const int kidx = r & 31;

    const float* row = &g_qkv[(size_t)(b * KSp + kidx) * D3];
    float2 q  = *reinterpret_cast<const float2*>(row + h * HDd + lane * 2);
    float2 kv = *reinterpret_cast<const float2*>(row + Dd + h * HDd + lane * 2);
    float p = q.x * kv.x + q.y * kv.y;
#pragma unroll
    for (int o = 16; o; o >>= 1) p += __shfl_xor_sync(0xffffffffu, p, o);

    float attn = p * 0.125f;
    float filt = 1.f / (1.f + expf(-sfilter[h * 32 + kidx]));
    attn *= filt;

    float a = fabsf(attn);
    float scale = fmaxf(a, 1e-6f);
    float sn = attn / scale;
    float gate = 1.f / (1.f + expf(-(a - 0.5f) * 10.f));
    float I = sn * (0.1f + 0.9f * gate);
    const float alpha = 1.0f / 12.5f;
    const float denom = 1.0f + alpha * 0.8f;
    float v = 0.f, w = 0.f;
#pragma unroll
    for (int s = 0; s < 2; s++) {
        float dv = v - (v * v * v) * (1.f / 3.f) - w + I;
        float vn = v + dv;
        float wn = (w + (vn + 0.7f) * alpha) / denom;
        v = fminf(fmaxf(vn, -3.f), 3.f);
        w = fminf(fmaxf(wn, -3.f), 3.f);
    }
    float fv = v * scale;

    float2 vs = *reinterpret_cast<const float2*>(row + 2 * Dd + h * HDd + lane * 2);
    *reinterpret_cast<float2*>(&g_vg[(size_t)(b * KSp + kidx) * Dd + h * HDd + lane * 2]) =
        make_float2(fv * vs.x, fv * vs.y);
}

// =====================================================================
// K5 (bf16 m16n8k16, 3-term, split-once): out[128t x 128e] = S * y
// Ap[kp][t] / Yp[kp][e], pad 136 (== 8 mod 32): frag LDS addr 8*tig+g
// conflict-free. Mainloop = pure LDS + 96 mma per warp (no cvt).
// =====================================================================
__global__ void __launch_bounds__(256, 2) k_expand(const float* __restrict__ S,
                                                   float* __restrict__ out) {
    const int e0  = blockIdx.x * 128;
    const int t0  = blockIdx.y * 128;
    const int b   = blockIdx.z;
    const int tid = threadIdx.x;

    __shared__ uint32_t Ap_hi[16][136];   // 8.7 KB each; S k-pairs, [kp][t]
    __shared__ uint32_t Ap_lo[16][136];
    __shared__ uint32_t Yp_hi[16][136];   // y k-pairs, [kp][e]
    __shared__ uint32_t Yp_lo[16][136];   // total 34.8 KB

    // stage S: thread owns t = tid>>1, spectral half kh = (tid&1)*16
    {
        const int t  = tid >> 1;
        const int kh = (tid & 1) * 16;
        const float* sp = S + ((size_t)b * Tt + t0 + t) * KSp + kh;
        float4 v0 = *reinterpret_cast<const float4*>(sp);
        float4 v1 = *reinterpret_cast<const float4*>(sp + 4);
        float4 v2 = *reinterpret_cast<const float4*>(sp + 8);
        float4 v3 = *reinterpret_cast<const float4*>(sp + 12);
        float v[16] = {v0.x, v0.y, v0.z, v0.w, v1.x, v1.y, v1.z, v1.w,
                       v2.x, v2.y, v2.z, v2.w, v3.x, v3.y, v3.z, v3.w};
#pragma unroll
        for (int j = 0; j < 8; j++) {
            uint32_t h, l;
            bf_split2(v[2 * j], v[2 * j + 1], h, l);   // low = even k
            Ap_hi[kh / 2 + j][t] = h;
            Ap_lo[kh / 2 + j][t] = l;
        }
    }
    // stage y: thread owns k-pair kp = tid>>4, e-cols ec..ec+7
    {
        const int kp = tid >> 4;
        const int ec = (tid & 15) * 8;
        const float* y0 = g_y + ((size_t)b * KSp + 2 * kp) * Dd + e0 + ec;
        float4 a0 = *reinterpret_cast<const float4*>(y0);
        float4 a1 = *reinterpret_cast<const float4*>(y0 + 4);
        float4 b0 = *reinterpret_cast<const float4*>(y0 + Dd);
        float4 b1 = *reinterpret_cast<const float4*>(y0 + Dd + 4);
        float p0[8] = {a0.x, a0.y, a0.z, a0.w, a1.x, a1.y, a1.z, a1.w};
        float p1[8] = {b0.x, b0.y, b0.z, b0.w, b1.x, b1.y, b1.z, b1.w};
        uint32_t hi[8], lo[8];
#pragma unroll
        for (int j = 0; j < 8; j++) bf_split2(p0[j], p1[j], hi[j], lo[j]);
        *reinterpret_cast<uint4*>(&Yp_hi[kp][ec]) =
            make_uint4(hi[0], hi[1], hi[2], hi[3]);
        *reinterpret_cast<uint4*>(&Yp_hi[kp][ec + 4]) =
            make_uint4(hi[4], hi[5], hi[6], hi[7]);
        *reinterpret_cast<uint4*>(&Yp_lo[kp][ec]) =
            make_uint4(lo[0], lo[1], lo[2], lo[3]);
        *reinterpret_cast<uint4*>(&Yp_lo[kp][ec + 4]) =
            make_uint4(lo[4], lo[5], lo[6], lo[7]);
    }
    __syncthreads();

    const int wid  = tid >> 5;
    const int lane = tid & 31;
    const int tw = (wid >> 1) * 32;
    const int ew = (wid & 1) * 64;
    const int g   = lane >> 2;
    const int tig = lane & 3;

    float c[2][8][4];
#pragma unroll
    for (int i = 0; i < 2; i++)
#pragma unroll
        for (int j = 0; j < 8; j++)
#pragma unroll
            for (int q = 0; q < 4; q++) c[i][j][q] = 0.f;

#pragma unroll
    for (int ks = 0; ks < 2; ks++) {
        const int kb = ks * 8;
        uint32_t ahi[2][4], alo[2][4];
#pragma unroll
        for (int mt = 0; mt < 2; mt++) {
            const int mr = tw + mt * 16 + g;
            ahi[mt][0] = Ap_hi[kb + tig][mr];
            ahi[mt][1] = Ap_hi[kb + tig][mr + 8];
            ahi[mt][2] = Ap_hi[kb + tig + 4][mr];
            ahi[mt][3] = Ap_hi[kb + tig + 4][mr + 8];
            alo[mt][0] = Ap_lo[kb + tig][mr];
            alo[mt][1] = Ap_lo[kb + tig][mr + 8];
            alo[mt][2] = Ap_lo[kb + tig + 4][mr];
            alo[mt][3] = Ap_lo[kb + tig + 4][mr + 8];
        }
#pragma unroll
        for (int nt = 0; nt < 8; nt++) {
            const int nb = ew + nt * 8 + g;
            uint32_t bhi[2], blo[2];
            bhi[0] = Yp_hi[kb + tig][nb];
            bhi[1] = Yp_hi[kb + tig + 4][nb];
            blo[0] = Yp_lo[kb + tig][nb];
            blo[1] = Yp_lo[kb + tig + 4][nb];
#pragma unroll
            for (int mt = 0; mt < 2; mt++) {
                mma_bf16(c[mt][nt], ahi[mt], bhi);
                mma_bf16(c[mt][nt], ahi[mt], blo);
                mma_bf16(c[mt][nt], alo[mt], bhi);
            }
        }
    }

#pragma unroll
    for (int mt = 0; mt < 2; mt++) {
        const int rbase = t0 + tw + mt * 16 + g;
#pragma unroll
        for (int nt = 0; nt < 8; nt++) {
            const int col = e0 + ew + nt * 8 + tig * 2;
            *reinterpret_cast<float2*>(
                &out[((size_t)b * Tt + rbase) * Dd + col]) =
                make_float2(c[mt][nt][0], c[mt][nt][1]);
            *reinterpret_cast<float2*>(
                &out[((size_t)b * Tt + rbase + 8) * Dd + col]) =
                make_float2(c[mt][nt][2], c[mt][nt][3]);
        }
    }
}

// =====================================================================
extern "C" void kernel_launch(void* const* d_in, const int* in_sizes, int n_in,
                              void* d_out, int out_size) {
    const float* x       = (const float*)d_in[0];
    const float* S       = (const float*)d_in[1];
    const float* w_qkv   = (const float*)d_in[2];
    const float* w_out   = (const float*)d_in[3];
    const float* sfilter = (const float*)d_in[4];
    float* out = (float*)d_out;

    // 1 nop puts k_gemm1 (never profiled) into the capture slot (#4)
    k_nop<<<1, 32>>>();
    k_project<<<dim3(3, NSEG, Bb), 256>>>(x, S);
    k_reduce<<<192, 256>>>();
    k_gemm1<<<dim3(D3 / 64, 4), 256>>>(w_qkv);
    k_fhn<<<384, 256>>>(sfilter);
    k_gemm2<<<dim3(Dd / 64, 4), 256>>>(w_out);
    k_expand<<<dim3(6, 32, Bb), 256>>>(S, out);
}

// round 14
// speedup vs baseline: 1.1960x; 1.1272x over previous
#include <cuda_runtime.h>
#include <cstdint>

#define Bb   8
#define Tt   4096
#define Dd   768
#define Hh   12
#define HDd  64
#define KSp  32
#define D3   2304
#define KP   384        // k-pairs per row (768/2)

#define NSEG 32
#define TSEG 128
#define TCH  16
#define CHUNKS (TSEG / TCH)   // 8

typedef unsigned long long u64;

// ---------------- scratch ----------------
__device__ float    g_partial[NSEG * Bb * KSp * Dd];   // 25.2 MB (L2-resident)
__device__ float    g_qkv[Bb * KSp * D3];
__device__ float    g_y[Bb * KSp * Dd];
__device__ uint32_t g_xs_hi[256 * KP], g_xs_lo[256 * KP];     // packed xs
__device__ uint32_t g_vg_hi[256 * KP], g_vg_lo[256 * KP];     // packed fv*v
__device__ uint32_t g_wq_hi[D3 * KP],  g_wq_lo[D3 * KP];      // packed w_qkv
__device__ uint32_t g_wo_hi[Dd * KP],  g_wo_lo[Dd * KP];      // packed w_out

// ---------------- bf16 helpers (R12/R13-verified) ----------------
__device__ __forceinline__ uint32_t bfpack(float h, float l) {
    uint32_t d;
    asm("cvt.rn.bf16x2.f32 %0, %1, %2;" : "=r"(d) : "f"(h), "f"(l));
    return d;
}
// split pair (x0 -> low half, x1 -> high half) into hi/lo bf16x2 words
__device__ __forceinline__ void bf_split2(float x0, float x1,
                                          uint32_t& hi, uint32_t& lo) {
    hi = bfpack(x1, x0);
    float l0 = __uint_as_float(hi << 16);
    float h0 = __uint_as_float(hi & 0xffff0000u);
    lo = bfpack(x1 - h0, x0 - l0);
}
__device__ __forceinline__ void mma_bf16(float* c, const uint32_t* a,
                                         const uint32_t* b) {
    asm("mma.sync.aligned.m16n8k16.row.col.f32.bf16.bf16.f32 "
        "{%0,%1,%2,%3}, {%4,%5,%6,%7}, {%8,%9}, {%0,%1,%2,%3};"
        : "+f"(c[0]), "+f"(c[1]), "+f"(c[2]), "+f"(c[3])
        : "r"(a[0]), "r"(a[1]), "r"(a[2]), "r"(a[3]), "r"(b[0]), "r"(b[1]));
}

// =====================================================================
// K0: split a weight matrix into packed hi/lo bf16x2 k-pair arrays
// thread handles 4 consecutive pairs (8 floats)
// =====================================================================
__global__ void k_wsplit(const float* __restrict__ src, int which) {
    uint32_t* hi = which ? g_wo_hi : g_wq_hi;
    uint32_t* lo = which ? g_wo_lo : g_wq_lo;
    const int i = blockIdx.x * blockDim.x + threadIdx.x;
    const float4* s = reinterpret_cast<const float4*>(src) + (size_t)i * 2;
    float4 v0 = s[0], v1 = s[1];
    uint32_t h[4], l[4];
    bf_split2(v0.x, v0.y, h[0], l[0]);
    bf_split2(v0.z, v0.w, h[1], l[1]);
    bf_split2(v1.x, v1.y, h[2], l[2]);
    bf_split2(v1.z, v1.w, h[3], l[3]);
    *reinterpret_cast<uint4*>(hi + (size_t)i * 4) = make_uint4(h[0], h[1], h[2], h[3]);
    *reinterpret_cast<uint4*>(lo + (size_t)i * 4) = make_uint4(l[0], l[1], l[2], l[3]);
}

// =====================================================================
// K1 (bf16 m16n8k16, 3-term): partial[seg][b][k][d] = sum_t S^T x
// (R12/R13 kernel, measured 37.0us, unchanged)
// =====================================================================
__global__ void __launch_bounds__(256) k_project(const float* __restrict__ x,
                                                 const float* __restrict__ S) {
    const int d0  = blockIdx.x * 256;
    const int t0  = blockIdx.y * TSEG;
    const int b   = blockIdx.z;
    const int tid = threadIdx.x;

    __shared__ uint32_t Ap_hi[KSp][68];
    __shared__ uint32_t Ap_lo[KSp][68];
    __shared__ uint32_t Xp_hi[8][264];
    __shared__ uint32_t Xp_lo[8][264];

    const int kk = tid >> 5;
    const int c  = (tid & 31) * 8;

    const float* xbase = x + ((size_t)b * Tt + t0) * Dd + d0;

    float4 xr[4];
    {
        const float* r0 = xbase + (size_t)(2 * kk) * Dd + c;
        xr[0] = *reinterpret_cast<const float4*>(r0);
        xr[1] = *reinterpret_cast<const float4*>(r0 + 4);
        xr[2] = *reinterpret_cast<const float4*>(r0 + Dd);
        xr[3] = *reinterpret_cast<const float4*>(r0 + Dd + 4);
    }

    {
        const int tp = tid & 63;
        const int mh = tid >> 6;
        const float* s0 = S + ((size_t)b * Tt + t0 + 2 * tp) * KSp + mh * 8;
        float4 A0 = *reinterpret_cast<const float4*>(s0);
        float4 A0b = *reinterpret_cast<const float4*>(s0 + 4);
        float4 A1 = *reinterpret_cast<const float4*>(s0 + KSp);
        float4 A1b = *reinterpret_cast<const float4*>(s0 + KSp + 4);
        float v0[8] = {A0.x, A0.y, A0.z, A0.w, A0b.x, A0b.y, A0b.z, A0b.w};
        float v1[8] = {A1.x, A1.y, A1.z, A1.w, A1b.x, A1b.y, A1b.z, A1b.w};
#pragma unroll
        for (int j = 0; j < 8; j++) {
            uint32_t h, l;
            bf_split2(v0[j], v1[j], h, l);
            Ap_hi[mh * 8 + j][tp] = h;
            Ap_lo[mh * 8 + j][tp] = l;
        }
    }

    const int wid  = tid >> 5;
    const int lane = tid & 31;
    const int nw   = wid * 32;
    const int g    = lane >> 2;
    const int tig  = lane & 3;

    float cacc[2][4][4];
#pragma unroll
    for (int i = 0; i < 2; i++)
#pragma unroll
        for (int j = 0; j < 4; j++)
#pragma unroll
            for (int q = 0; q < 4; q++) cacc[i][j][q] = 0.f;

    for (int ch = 0; ch < CHUNKS; ch++) {
        __syncthreads();
        {
            float x0[8] = {xr[0].x, xr[0].y, xr[0].z, xr[0].w,
                           xr[1].x, xr[1].y, xr[1].z, xr[1].w};
            float x1[8] = {xr[2].x, xr[2].y, xr[2].z, xr[2].w,
                           xr[3].x, xr[3].y, xr[3].z, xr[3].w};
            uint32_t hi[8], lo[8];
#pragma unroll
            for (int j = 0; j < 8; j++) bf_split2(x0[j], x1[j], hi[j], lo[j]);
            *reinterpret_cast<uint4*>(&Xp_hi[kk][c]) =
                make_uint4(hi[0], hi[1], hi[2], hi[3]);
            *reinterpret_cast<uint4*>(&Xp_hi[kk][c + 4]) =
                make_uint4(hi[4], hi[5], hi[6], hi[7]);
            *reinterpret_cast<uint4*>(&Xp_lo[kk][c]) =
                make_uint4(lo[0], lo[1], lo[2], lo[3]);
            *reinterpret_cast<uint4*>(&Xp_lo[kk][c + 4]) =
                make_uint4(lo[4], lo[5], lo[6], lo[7]);
        }
        __syncthreads();
        if (ch + 1 < CHUNKS) {
            const float* r0 = xbase + (size_t)((ch + 1) * TCH + 2 * kk) * Dd + c;
            xr[0] = *reinterpret_cast<const float4*>(r0);
            xr[1] = *reinterpret_cast<const float4*>(r0 + 4);
            xr[2] = *reinterpret_cast<const float4*>(r0 + Dd);
            xr[3] = *reinterpret_cast<const float4*>(r0 + Dd + 4);
        }
        const int tc2 = ch * 8;
        uint32_t ahi[2][4], alo[2][4];
#pragma unroll
        for (int mt = 0; mt < 2; mt++) {
            const int mb = mt * 16;
            ahi[mt][0] = Ap_hi[mb + g][tc2 + tig];
            ahi[mt][1] = Ap_hi[mb + g + 8][tc2 + tig];
            ahi[mt][2] = Ap_hi[mb + g][tc2 + tig + 4];
            ahi[mt][3] = Ap_hi[mb + g + 8][tc2 + tig + 4];
            alo[mt][0] = Ap_lo[mb + g][tc2 + tig];
            alo[mt][1] = Ap_lo[mb + g + 8][tc2 + tig];
            alo[mt][2] = Ap_lo[mb + g][tc2 + tig + 4];
            alo[mt][3] = Ap_lo[mb + g + 8][tc2 + tig + 4];
        }
#pragma unroll
        for (int nt = 0; nt < 4; nt++) {
            const int nb = nw + nt * 8;
            uint32_t bhi[2], blo[2];
            bhi[0] = Xp_hi[tig][nb + g];
            bhi[1] = Xp_hi[tig + 4][nb + g];
            blo[0] = Xp_lo[tig][nb + g];
            blo[1] = Xp_lo[tig + 4][nb + g];
#pragma unroll
            for (int mt = 0; mt < 2; mt++) {
                mma_bf16(cacc[mt][nt], ahi[mt], bhi);
                mma_bf16(cacc[mt][nt], ahi[mt], blo);
                mma_bf16(cacc[mt][nt], alo[mt], bhi);
            }
        }
    }

    float* pb = &g_partial[(((size_t)blockIdx.y * Bb + b) * KSp) * Dd + d0];
#pragma unroll
    for (int mt = 0; mt < 2; mt++) {
        const int r0 = mt * 16 + g;
#pragma unroll
        for (int nt = 0; nt < 4; nt++) {
            const int col = nw + nt * 8 + tig * 2;
            *reinterpret_cast<float2*>(pb + (size_t)r0 * Dd + col) =
                make_float2(cacc[mt][nt][0], cacc[mt][nt][1]);
            *reinterpret_cast<float2*>(pb + (size_t)(r0 + 8) * Dd + col) =
                make_float2(cacc[mt][nt][2], cacc[mt][nt][3]);
        }
    }
}

// =====================================================================
// K2: xs = sum over 32 segments; emit packed hi/lo bf16x2 k-pairs
// =====================================================================
__global__ void k_reduce() {
    const int i = blockIdx.x * blockDim.x + threadIdx.x;   // float4 idx, 49152
    const int stride4 = (Bb * KSp * Dd) / 4;
    const float4* p = reinterpret_cast<const float4*>(g_partial);
    float4 s = make_float4(0.f, 0.f, 0.f, 0.f);
#pragma unroll
    for (int seg = 0; seg < NSEG; seg++) {
        float4 v = p[(size_t)seg * stride4 + i];
        s.x += v.x; s.y += v.y; s.z += v.z; s.w += v.w;
    }
    uint32_t h0, l0, h1, l1;
    bf_split2(s.x, s.y, h0, l0);
    bf_split2(s.z, s.w, h1, l1);
    const int row = i / 192;          // 192 float4 per row
    const int c4  = i % 192;
    *reinterpret_cast<uint2*>(&g_xs_hi[(size_t)row * KP + c4 * 2]) = make_uint2(h0, h1);
    *reinterpret_cast<uint2*>(&g_xs_lo[(size_t)row * KP + c4 * 2]) = make_uint2(l0, l1);
}

// =====================================================================
// bf16 GEMM: C[256, N] = A[256, 768] * W[N, 768]^T  with pre-packed
// operands. Block 32m x 64n, 256 thr, warp tile 16m x 16n, K chunk 32.
// Mainloop: pure LDS + mma (no conversions). Pads 20 -> frag banks
// 20g + tig all-distinct (conflict-free).
// =====================================================================
__device__ __forceinline__ void gemmb_body(const uint32_t* __restrict__ Ahi,
                                           const uint32_t* __restrict__ Alo,
                                           const uint32_t* __restrict__ Whi,
                                           const uint32_t* __restrict__ Wlo,
                                           float* __restrict__ C, int N,
                                           int n0, int m0, int tid) {
    __shared__ uint32_t Ap_hi[32][20], Ap_lo[32][20];
    __shared__ uint32_t Wp_hi[64][20], Wp_lo[64][20];   // 15.4 KB total

    const int ra = tid >> 3, kpa = (tid & 7) * 2;
    const int rw = tid >> 2, kpw = (tid & 3) * 4;

    uint2 pa_h = *reinterpret_cast<const uint2*>(&Ahi[(size_t)(m0 + ra) * KP + kpa]);
    uint2 pa_l = *reinterpret_cast<const uint2*>(&Alo[(size_t)(m0 + ra) * KP + kpa]);
    uint4 pw_h = *reinterpret_cast<const uint4*>(&Whi[(size_t)(n0 + rw) * KP + kpw]);
    uint4 pw_l = *reinterpret_cast<const uint4*>(&Wlo[(size_t)(n0 + rw) * KP + kpw]);

    const int wid  = tid >> 5;
    const int lane = tid & 31;
    const int wm = (wid >> 2) * 16;   // 0 | 16
    const int wn = (wid & 3) * 16;    // 0..48
    const int g  = lane >> 2;
    const int tig = lane & 3;

    float acc[2][4];
#pragma unroll
    for (int i = 0; i < 2; i++)
#pragma unroll
        for (int q = 0; q < 4; q++) acc[i][q] = 0.f;

    for (int ch = 0; ch < 24; ch++) {
        *reinterpret_cast<uint2*>(&Ap_hi[ra][kpa]) = pa_h;
        *reinterpret_cast<uint2*>(&Ap_lo[ra][kpa]) = pa_l;
        *reinterpret_cast<uint4*>(&Wp_hi[rw][kpw]) = pw_h;
        *reinterpret_cast<uint4*>(&Wp_lo[rw][kpw]) = pw_l;
        __syncthreads();
        if (ch + 1 < 24) {
            const int kb2 = (ch + 1) * 16;
            pa_h = *reinterpret_cast<const uint2*>(&Ahi[(size_t)(m0 + ra) * KP + kb2 + kpa]);
            pa_l = *reinterpret_cast<const uint2*>(&Alo[(size_t)(m0 + ra) * KP + kb2 + kpa]);
            pw_h = *reinterpret_cast<const uint4*>(&Whi[(size_t)(n0 + rw) * KP + kb2 + kpw]);
            pw_l = *reinterpret_cast<const uint4*>(&Wlo[(size_t)(n0 + rw) * KP + kb2 + kpw]);
        }
#pragma unroll
        for (int kb = 0; kb < 16; kb += 8) {
            uint32_t ahi[4], alo[4];
            ahi[0] = Ap_hi[wm + g][kb + tig];
            ahi[1] = Ap_hi[wm + g + 8][kb + tig];
            ahi[2] = Ap_hi[wm + g][kb + tig + 4];
            ahi[3] = Ap_hi[wm + g + 8][kb + tig + 4];
            alo[0] = Ap_lo[wm + g][kb + tig];
            alo[1] = Ap_lo[wm + g + 8][kb + tig];
            alo[2] = Ap_lo[wm + g][kb + tig + 4];
            alo[3] = Ap_lo[wm + g + 8][kb + tig + 4];
#pragma unroll
            for (int nt = 0; nt < 2; nt++) {
                const int nb = wn + nt * 8 + g;
                uint32_t bhi[2], blo[2];
                bhi[0] = Wp_hi[nb][kb + tig];
                bhi[1] = Wp_hi[nb][kb + tig + 4];
                blo[0] = Wp_lo[nb][kb + tig];
                blo[1] = Wp_lo[nb][kb + tig + 4];
                mma_bf16(acc[nt], ahi, bhi);
                mma_bf16(acc[nt], ahi, blo);
                mma_bf16(acc[nt], alo, bhi);
            }
        }
        __syncthreads();
    }

#pragma unroll
    for (int nt = 0; nt < 2; nt++) {
        const int col = n0 + wn + nt * 8 + tig * 2;
        *reinterpret_cast<float2*>(&C[(size_t)(m0 + wm + g) * N + col]) =
            make_float2(acc[nt][0], acc[nt][1]);
        *reinterpret_cast<float2*>(&C[(size_t)(m0 + wm + g + 8) * N + col]) =
            make_float2(acc[nt][2], acc[nt][3]);
    }
}

__global__ void __launch_bounds__(256) k_gemm1() {
    gemmb_body(g_xs_hi, g_xs_lo, g_wq_hi, g_wq_lo, g_qkv, D3,
               blockIdx.x * 64, blockIdx.y * 32, threadIdx.x);
}
__global__ void __launch_bounds__(256) k_gemm2() {
    gemmb_body(g_vg_hi, g_vg_lo, g_wo_hi, g_wo_lo, g_y, Dd,
               blockIdx.x * 64, blockIdx.y * 32, threadIdx.x);
}

// =====================================================================
// K_fhn: one warp per (b,h,k); emits packed hi/lo vg k-pair directly
// =====================================================================
__global__ void __launch_bounds__(256) k_fhn(const float* __restrict__ sfilter) {
    const int tid  = threadIdx.x;
    const int lane = tid & 31;
    const int idx  = blockIdx.x * 8 + (tid >> 5);
    const int b    = idx / (Hh * KSp);
    const int r    = idx % (Hh * KSp);
    const int h    = r >> 5;
    const int kidx = r & 31;

    const float* row = &g_qkv[(size_t)(b * KSp + kidx) * D3];
    float2 q  = *reinterpret_cast<const float2*>(row + h * HDd + lane * 2);
    float2 kv = *reinterpret_cast<const float2*>(row + Dd + h * HDd + lane * 2);
    float p = q.x * kv.x + q.y * kv.y;
#pragma unroll
    for (int o = 16; o; o >>= 1) p += __shfl_xor_sync(0xffffffffu, p, o);

    float attn = p * 0.125f;
    float filt = 1.f / (1.f + expf(-sfilter[h * 32 + kidx]));
    attn *= filt;

    float a = fabsf(attn);
    float scale = fmaxf(a, 1e-6f);
    float sn = attn / scale;
    float gate = 1.f / (1.f + expf(-(a - 0.5f) * 10.f));
    float I = sn * (0.1f + 0.9f * gate);
    const float alpha = 1.0f / 12.5f;
    const float denom = 1.0f + alpha * 0.8f;
    float v = 0.f, w = 0.f;
#pragma unroll
    for (int s = 0; s < 2; s++) {
        float dv = v - (v * v * v) * (1.f / 3.f) - w + I;
        float vn = v + dv;
        float wn = (w + (vn + 0.7f) * alpha) / denom;
        v = fminf(fmaxf(vn, -3.f), 3.f);
        w = fminf(fmaxf(wn, -3.f), 3.f);
    }
    float fv = v * scale;

    float2 vs = *reinterpret_cast<const float2*>(row + 2 * Dd + h * HDd + lane * 2);
    uint32_t hh, ll;
    bf_split2(fv * vs.x, fv * vs.y, hh, ll);
    const size_t pi = (size_t)(b * KSp + kidx) * KP + h * 32 + lane;
    g_vg_hi[pi] = hh;
    g_vg_lo[pi] = ll;
}

// =====================================================================
// K5 (bf16 m16n8k16, 3-term, split-once): out[128t x 128e] = S * y
// (R13 kernel, unchanged)
// =====================================================================
__global__ void __launch_bounds__(256, 2) k_expand(const float* __restrict__ S,
                                                   float* __restrict__ out) {
    const int e0  = blockIdx.x * 128;
    const int t0  = blockIdx.y * 128;
    const int b   = blockIdx.z;
    const int tid = threadIdx.x;

    __shared__ uint32_t Ap_hi[16][136];
    __shared__ uint32_t Ap_lo[16][136];
    __shared__ uint32_t Yp_hi[16][136];
    __shared__ uint32_t Yp_lo[16][136];

    {
        const int t  = tid >> 1;
        const int kh = (tid & 1) * 16;
        const float* sp = S + ((size_t)b * Tt + t0 + t) * KSp + kh;
        float4 v0 = *reinterpret_cast<const float4*>(sp);
        float4 v1 = *reinterpret_cast<const float4*>(sp + 4);
        float4 v2 = *reinterpret_cast<const float4*>(sp + 8);
        float4 v3 = *reinterpret_cast<const float4*>(sp + 12);
        float v[16] = {v0.x, v0.y, v0.z, v0.w, v1.x, v1.y, v1.z, v1.w,
                       v2.x, v2.y, v2.z, v2.w, v3.x, v3.y, v3.z, v3.w};
#pragma unroll
        for (int j = 0; j < 8; j++) {
            uint32_t h, l;
            bf_split2(v[2 * j], v[2 * j + 1], h, l);
            Ap_hi[kh / 2 + j][t] = h;
            Ap_lo[kh / 2 + j][t] = l;
        }
    }
    {
        const int kp = tid >> 4;
        const int ec = (tid & 15) * 8;
        const float* y0 = g_y + ((size_t)b * KSp + 2 * kp) * Dd + e0 + ec;
        float4 a0 = *reinterpret_cast<const float4*>(y0);
        float4 a1 = *reinterpret_cast<const float4*>(y0 + 4);
        float4 b0 = *reinterpret_cast<const float4*>(y0 + Dd);
        float4 b1 = *reinterpret_cast<const float4*>(y0 + Dd + 4);
        float p0[8] = {a0.x, a0.y, a0.z, a0.w, a1.x, a1.y, a1.z, a1.w};
        float p1[8] = {b0.x, b0.y, b0.z, b0.w, b1.x, b1.y, b1.z, b1.w};
        uint32_t hi[8], lo[8];
#pragma unroll
        for (int j = 0; j < 8; j++) bf_split2(p0[j], p1[j], hi[j], lo[j]);
        *reinterpret_cast<uint4*>(&Yp_hi[kp][ec]) =
            make_uint4(hi[0], hi[1], hi[2], hi[3]);
        *reinterpret_cast<uint4*>(&Yp_hi[kp][ec + 4]) =
            make_uint4(hi[4], hi[5], hi[6], hi[7]);
        *reinterpret_cast<uint4*>(&Yp_lo[kp][ec]) =
            make_uint4(lo[0], lo[1], lo[2], lo[3]);
        *reinterpret_cast<uint4*>(&Yp_lo[kp][ec + 4]) =
            make_uint4(lo[4], lo[5], lo[6], lo[7]);
    }
    __syncthreads();

    const int wid  = tid >> 5;
    const int lane = tid & 31;
    const int tw = (wid >> 1) * 32;
    const int ew = (wid & 1) * 64;
    const int g   = lane >> 2;
    const int tig = lane & 3;

    float c[2][8][4];
#pragma unroll
    for (int i = 0; i < 2; i++)
#pragma unroll
        for (int j = 0; j < 8; j++)
#pragma unroll
            for (int q = 0; q < 4; q++) c[i][j][q] = 0.f;

#pragma unroll
    for (int ks = 0; ks < 2; ks++) {
        const int kb = ks * 8;
        uint32_t ahi[2][4], alo[2][4];
#pragma unroll
        for (int mt = 0; mt < 2; mt++) {
            const int mr = tw + mt * 16 + g;
            ahi[mt][0] = Ap_hi[kb + tig][mr];
            ahi[mt][1] = Ap_hi[kb + tig][mr + 8];
            ahi[mt][2] = Ap_hi[kb + tig + 4][mr];
            ahi[mt][3] = Ap_hi[kb + tig + 4][mr + 8];
            alo[mt][0] = Ap_lo[kb + tig][mr];
            alo[mt][1] = Ap_lo[kb + tig][mr + 8];
            alo[mt][2] = Ap_lo[kb + tig + 4][mr];
            alo[mt][3] = Ap_lo[kb + tig + 4][mr + 8];
        }
#pragma unroll
        for (int nt = 0; nt < 8; nt++) {
            const int nb = ew + nt * 8 + g;
            uint32_t bhi[2], blo[2];
            bhi[0] = Yp_hi[kb + tig][nb];
            bhi[1] = Yp_hi[kb + tig + 4][nb];
            blo[0] = Yp_lo[kb + tig][nb];
            blo[1] = Yp_lo[kb + tig + 4][nb];
#pragma unroll
            for (int mt = 0; mt < 2; mt++) {
                mma_bf16(c[mt][nt], ahi[mt], bhi);
                mma_bf16(c[mt][nt], ahi[mt], blo);
                mma_bf16(c[mt][nt], alo[mt], bhi);
            }
        }
    }

#pragma unroll
    for (int mt = 0; mt < 2; mt++) {
        const int rbase = t0 + tw + mt * 16 + g;
#pragma unroll
        for (int nt = 0; nt < 8; nt++) {
            const int col = e0 + ew + nt * 8 + tig * 2;
            *reinterpret_cast<float2*>(
                &out[((size_t)b * Tt + rbase) * Dd + col]) =
                make_float2(c[mt][nt][0], c[mt][nt][1]);
            *reinterpret_cast<float2*>(
                &out[((size_t)b * Tt + rbase + 8) * Dd + col]) =
                make_float2(c[mt][nt][2], c[mt][nt][3]);
        }
    }
}

// =====================================================================
extern "C" void kernel_launch(void* const* d_in, const int* in_sizes, int n_in,
                              void* d_out, int out_size) {
    const float* x       = (const float*)d_in[0];
    const float* S       = (const float*)d_in[1];
    const float* w_qkv   = (const float*)d_in[2];
    const float* w_out   = (const float*)d_in[3];
    const float* sfilter = (const float*)d_in[4];
    float* out = (float*)d_out;

    // launch #4 = new bf16 k_gemm1 (profiler capture slot)
    k_wsplit<<<864, 256>>>(w_qkv, 0);                  // 2304*384/4/256
    k_project<<<dim3(3, NSEG, Bb), 256>>>(x, S);
    k_reduce<<<192, 256>>>();
    k_gemm1<<<dim3(D3 / 64, 8), 256>>>();
    k_wsplit<<<288, 256>>>(w_out, 1);                  // 768*384/4/256
    k_fhn<<<384, 256>>>(sfilter);
    k_gemm2<<<dim3(Dd / 64, 8), 256>>>();
    k_expand<<<dim3(6, 32, Bb), 256>>>(S, out);
}